// round 4
// baseline (speedup 1.0000x reference)
#include <cuda_runtime.h>
#include <cstdint>
#include <math.h>

// Problem constants
#define P     48
#define FLEN  168
#define HALF  84     // t-split: each CTA handles one half of the forecast horizon
#define HIST  336
#define HOFF  288    // HIST - P

// Precomputed affine map: out[b,t] = g_C[t] + sum_k g_G[k*FLEN+t] * enc_l[b*HIST+HOFF+k]
__device__ float g_G[P * FLEN];
__device__ float g_C[FLEN];
__device__ float g_lv;

typedef unsigned long long ull;

__device__ __forceinline__ ull pack2(float a, float b) {
    ull r; asm("mov.b64 %0, {%1, %2};" : "=l"(r) : "f"(a), "f"(b)); return r;
}
__device__ __forceinline__ void unpack2(ull v, float& a, float& b) {
    asm("mov.b64 {%0, %1}, %2;" : "=f"(a), "=f"(b) : "l"(v));
}
// Packed fp32x2 FMA (Blackwell 2x fp32 path; only emitted from PTX fma.rn.f32x2)
__device__ __forceinline__ ull ffma2(ull a, ull b, ull c) {
    ull d; asm("fma.rn.f32x2 %0, %1, %2, %3;" : "=l"(d) : "l"(a), "l"(b), "l"(c)); return d;
}

// ---------------------------------------------------------------------------
// Kernel 1: tiny precompute of the affine map (G, C, logvar const).
// ---------------------------------------------------------------------------
__global__ void precompute_kernel(const float* __restrict__ phi,
                                  const float* __restrict__ bias,
                                  const float* __restrict__ log_sigma2,
                                  const float* __restrict__ mu_p,
                                  const float* __restrict__ sigma_p) {
    __shared__ float h[P + 1][221];   // 221 odd pitch -> conflict-free
    const int k = threadIdx.x;

    float ph[P];
#pragma unroll
    for (int j = 0; j < P; j++) ph[j] = phi[j];

    if (k <= P) {
#pragma unroll
        for (int i = 0; i < P; i++) h[k][i] = (k == i) ? 1.0f : 0.0f;  // k==P row: zeros
        const float b0 = (k == P) ? bias[0] : 0.0f;
        for (int t = 0; t < FLEN; t++) {
            float s0 = 0.f, s1 = 0.f, s2 = 0.f, s3 = 0.f;
#pragma unroll
            for (int j = 0; j < P; j += 4) {
                s0 += ph[j + 0] * h[k][t + j + 0];
                s1 += ph[j + 1] * h[k][t + j + 1];
                s2 += ph[j + 2] * h[k][t + j + 2];
                s3 += ph[j + 3] * h[k][t + j + 3];
            }
            h[k][P + t] = b0 + ((s0 + s1) + (s2 + s3));
        }
    }
    __syncthreads();

    const float mu = *mu_p;
    const float sg = *sigma_p;

    for (int t = threadIdx.x; t < FLEN; t += blockDim.x) {
        float sum = 0.0f;
        for (int kk = 0; kk < P; kk++) sum += h[kk][P + t];
        g_C[t] = mu + sg * h[P][P + t] - mu * sum;
    }
    for (int idx = threadIdx.x; idx < P * FLEN; idx += blockDim.x) {
        const int kk = idx / FLEN;
        const int t  = idx - kk * FLEN;
        g_G[idx] = h[kk][P + t];
    }
    if (threadIdx.x == 0) g_lv = log_sigma2[0] + 2.0f * logf(sg);
}

// ---------------------------------------------------------------------------
// Kernel 2: register-blocked GEMM. C[B x 168] = Y[B x 48] * G[48 x 168].
// Each thread computes a 4-row x 12-t register tile; per k: 4 LDS.128 feed
// 24 FFMA2 (1:6), vs 1:2 in the previous (smem-bandwidth-bound) version.
// CTA tile = 128 rows x 84 t. Y staged transposed in smem (pitch 132).
// ---------------------------------------------------------------------------
#define TPB   224     // 32 row-threads x 7 t-threads
#define YPITCH 132

__global__ void __launch_bounds__(TPB, 3)
forecast_kernel(const float* __restrict__ enc_l, float* __restrict__ out, int B) {
    __shared__ float Ys[P * YPITCH];  // Ys[k*YPITCH + row], transposed Y tile
    __shared__ float Gs[P * HALF];    // Gs[k*HALF + tt]
    __shared__ float Cs[HALF];

    const int half = blockIdx.x & 1;
    const int rb   = blockIdx.x >> 1;
    const int toff = half * HALF;
    const int brow0 = rb * 128;

    // --- Stage G half-slice + C ---
    for (int i = threadIdx.x; i < P * (HALF / 4); i += TPB) {
        const int kk = i / (HALF / 4);
        const int j4 = i - kk * (HALF / 4);
        *(float4*)(Gs + kk * HALF + j4 * 4) =
            *(const float4*)(g_G + kk * FLEN + toff + j4 * 4);
    }
    if (threadIdx.x < HALF) Cs[threadIdx.x] = g_C[toff + threadIdx.x];

    // --- Stage Y tile transposed: Ys[k][r] = enc_l[(brow0+r)*HIST + HOFF + k] ---
    for (int i = threadIdx.x; i < 128 * (P / 4); i += TPB) {
        const int r  = i / (P / 4);
        const int j4 = i - r * (P / 4);
        const int gr = brow0 + r;
        float4 v = (gr < B)
            ? *(const float4*)(enc_l + (size_t)gr * HIST + HOFF + j4 * 4)
            : make_float4(0.f, 0.f, 0.f, 0.f);
        Ys[(4 * j4 + 0) * YPITCH + r] = v.x;
        Ys[(4 * j4 + 1) * YPITCH + r] = v.y;
        Ys[(4 * j4 + 2) * YPITCH + r] = v.z;
        Ys[(4 * j4 + 3) * YPITCH + r] = v.w;
    }
    __syncthreads();

    const int tr = threadIdx.x & 31;          // row-thread: rows r0..r0+3
    const int tc = threadIdx.x >> 5;          // t-thread (warp id): t = tc*12..+11
    const int r0 = tr * 4;
    const int t0 = tc * 12;

    // acc[ri][j]: 4 rows x 6 packed t-pairs, init from C (same for all rows)
    ull acc[4][6];
    {
        const ull* cp = (const ull*)(Cs + t0);    // 8B-aligned (48*tc)
        ull c0 = cp[0], c1 = cp[1], c2 = cp[2], c3 = cp[3], c4 = cp[4], c5 = cp[5];
#pragma unroll
        for (int ri = 0; ri < 4; ri++) {
            acc[ri][0] = c0; acc[ri][1] = c1; acc[ri][2] = c2;
            acc[ri][3] = c3; acc[ri][4] = c4; acc[ri][5] = c5;
        }
    }

#pragma unroll 4
    for (int k = 0; k < P; ++k) {
        // a-frag: 4 consecutive rows' y[k] (contiguous 16B, conflict-free)
        const float4 av = *(const float4*)(Ys + k * YPITCH + r0);
        // b-frag: 12 G values = 6 packed t-pairs (warp-broadcast LDS.128)
        const ull* gp = (const ull*)(Gs + k * HALF + t0);  // 16B-aligned
        const ull g0 = gp[0], g1 = gp[1], g2 = gp[2], g3 = gp[3], g4 = gp[4], g5 = gp[5];

        const ull y0 = pack2(av.x, av.x);
        const ull y1 = pack2(av.y, av.y);
        const ull y2 = pack2(av.z, av.z);
        const ull y3 = pack2(av.w, av.w);

        acc[0][0] = ffma2(g0, y0, acc[0][0]); acc[0][1] = ffma2(g1, y0, acc[0][1]);
        acc[0][2] = ffma2(g2, y0, acc[0][2]); acc[0][3] = ffma2(g3, y0, acc[0][3]);
        acc[0][4] = ffma2(g4, y0, acc[0][4]); acc[0][5] = ffma2(g5, y0, acc[0][5]);
        acc[1][0] = ffma2(g0, y1, acc[1][0]); acc[1][1] = ffma2(g1, y1, acc[1][1]);
        acc[1][2] = ffma2(g2, y1, acc[1][2]); acc[1][3] = ffma2(g3, y1, acc[1][3]);
        acc[1][4] = ffma2(g4, y1, acc[1][4]); acc[1][5] = ffma2(g5, y1, acc[1][5]);
        acc[2][0] = ffma2(g0, y2, acc[2][0]); acc[2][1] = ffma2(g1, y2, acc[2][1]);
        acc[2][2] = ffma2(g2, y2, acc[2][2]); acc[2][3] = ffma2(g3, y2, acc[2][3]);
        acc[2][4] = ffma2(g4, y2, acc[2][4]); acc[2][5] = ffma2(g5, y2, acc[2][5]);
        acc[3][0] = ffma2(g0, y3, acc[3][0]); acc[3][1] = ffma2(g1, y3, acc[3][1]);
        acc[3][2] = ffma2(g2, y3, acc[3][2]); acc[3][3] = ffma2(g3, y3, acc[3][3]);
        acc[3][4] = ffma2(g4, y3, acc[3][4]); acc[3][5] = ffma2(g5, y3, acc[3][5]);
    }

    // --- Epilogue: mu + constant logvar ---
    const float lv = g_lv;
    const float4 lv4 = make_float4(lv, lv, lv, lv);
#pragma unroll
    for (int ri = 0; ri < 4; ri++) {
        const int row = brow0 + r0 + ri;
        if (row >= B) break;
        float r[12];
#pragma unroll
        for (int j = 0; j < 6; j++) unpack2(acc[ri][j], r[2 * j], r[2 * j + 1]);
        float4* w = (float4*)(out + (size_t)row * FLEN + toff + t0);  // 16B-aligned
        w[0] = make_float4(r[0], r[1], r[2],  r[3]);
        w[1] = make_float4(r[4], r[5], r[6],  r[7]);
        w[2] = make_float4(r[8], r[9], r[10], r[11]);
        float4* q = (float4*)(out + (size_t)B * FLEN + (size_t)row * FLEN + toff + t0);
        q[0] = lv4; q[1] = lv4; q[2] = lv4;
    }
}

// ---------------------------------------------------------------------------
extern "C" void kernel_launch(void* const* d_in, const int* in_sizes, int n_in,
                              void* d_out, int out_size) {
    const float* enc_l      = (const float*)d_in[0];
    // d_in[1..3] = enc_t, enc_w, enc_s (unused by the reference)
    const float* phi        = (const float*)d_in[4];
    const float* bias       = (const float*)d_in[5];
    const float* log_sigma2 = (const float*)d_in[6];
    const float* mu         = (const float*)d_in[7];
    const float* sigma      = (const float*)d_in[8];

    const int B = in_sizes[0] / HIST;

    precompute_kernel<<<1, 64>>>(phi, bias, log_sigma2, mu, sigma);

    const int nblk = 2 * ((B + 127) / 128);   // x2: t-halves
    forecast_kernel<<<nblk, TPB>>>(enc_l, (float*)d_out, B);
}

// round 5
// speedup vs baseline: 1.3746x; 1.3746x over previous
#include <cuda_runtime.h>
#include <cstdint>
#include <math.h>

// Problem constants
#define P     48
#define FLEN  168
#define HALF  84     // t-split: each CTA handles one half of the forecast horizon
#define HIST  336
#define HOFF  288    // HIST - P

// Precomputed affine map: out[b,t] = g_C[t] + sum_k g_G[k*FLEN+t] * enc_l[b*HIST+HOFF+k]
__device__ float g_G[P * FLEN];
__device__ float g_C[FLEN];
__device__ float g_lv;

typedef unsigned long long ull;

__device__ __forceinline__ ull pack2(float a, float b) {
    ull r; asm("mov.b64 %0, {%1, %2};" : "=l"(r) : "f"(a), "f"(b)); return r;
}
__device__ __forceinline__ void unpack2(ull v, float& a, float& b) {
    asm("mov.b64 {%0, %1}, %2;" : "=f"(a), "=f"(b) : "l"(v));
}
// Packed fp32x2 FMA (Blackwell 2x fp32 path; only emitted from PTX fma.rn.f32x2)
__device__ __forceinline__ ull ffma2(ull a, ull b, ull c) {
    ull d; asm("fma.rn.f32x2 %0, %1, %2, %3;" : "=l"(d) : "l"(a), "l"(b), "l"(c)); return d;
}

// ---------------------------------------------------------------------------
// Kernel 1: tiny precompute of the affine map (G, C, logvar const).
// ---------------------------------------------------------------------------
__global__ void precompute_kernel(const float* __restrict__ phi,
                                  const float* __restrict__ bias,
                                  const float* __restrict__ log_sigma2,
                                  const float* __restrict__ mu_p,
                                  const float* __restrict__ sigma_p) {
    __shared__ float h[P + 1][221];   // 221 odd pitch -> conflict-free
    const int k = threadIdx.x;

    float ph[P];
#pragma unroll
    for (int j = 0; j < P; j++) ph[j] = phi[j];

    if (k <= P) {
#pragma unroll
        for (int i = 0; i < P; i++) h[k][i] = (k == i) ? 1.0f : 0.0f;  // k==P row: zeros
        const float b0 = (k == P) ? bias[0] : 0.0f;
        for (int t = 0; t < FLEN; t++) {
            float s0 = 0.f, s1 = 0.f, s2 = 0.f, s3 = 0.f;
#pragma unroll
            for (int j = 0; j < P; j += 4) {
                s0 += ph[j + 0] * h[k][t + j + 0];
                s1 += ph[j + 1] * h[k][t + j + 1];
                s2 += ph[j + 2] * h[k][t + j + 2];
                s3 += ph[j + 3] * h[k][t + j + 3];
            }
            h[k][P + t] = b0 + ((s0 + s1) + (s2 + s3));
        }
    }
    __syncthreads();

    const float mu = *mu_p;
    const float sg = *sigma_p;

    for (int t = threadIdx.x; t < FLEN; t += blockDim.x) {
        float sum = 0.0f;
        for (int kk = 0; kk < P; kk++) sum += h[kk][P + t];
        g_C[t] = mu + sg * h[P][P + t] - mu * sum;
    }
    for (int idx = threadIdx.x; idx < P * FLEN; idx += blockDim.x) {
        const int kk = idx / FLEN;
        const int t  = idx - kk * FLEN;
        g_G[idx] = h[kk][P + t];
    }
    if (threadIdx.x == 0) g_lv = log_sigma2[0] + 2.0f * logf(sg);
}

// ---------------------------------------------------------------------------
// Kernel 2: register-blocked GEMM with a COALESCED epilogue.
// Mainloop: 4-row x 12-t register tile per thread (24 FFMA2 per 4 LDS.128).
// Rounds 1-4 were L1-wavefront-bound on fragmented row-per-lane STGs
// (32 lines per warp-store). Fix: stage the mu tile in smem, then store
// cooperatively with lanes covering consecutive float4 within each row.
// ---------------------------------------------------------------------------
#define TPB    224    // 32 row-threads x 7 t-warps
#define YPITCH 132
#define CPITCH 84     // staging pitch (multiple of 4 -> float4-aligned rows)

// smem union: [Ys | Gs | Cs] during mainloop, [Co] during epilogue
#define YS_OFF 0
#define GS_OFF (P * YPITCH * 4)                    // 25344
#define CS_OFF (GS_OFF + P * HALF * 4)             // 41472
#define ML_BYTES (CS_OFF + HALF * 4)               // 41808
#define CO_BYTES (128 * CPITCH * 4)                // 43008
#define SMEM_BYTES (CO_BYTES > ML_BYTES ? CO_BYTES : ML_BYTES)

__global__ void __launch_bounds__(TPB, 3)
forecast_kernel(const float* __restrict__ enc_l, float* __restrict__ out, int B) {
    __shared__ __align__(16) char smem_buf[SMEM_BYTES];
    float* Ys = (float*)(smem_buf + YS_OFF);   // Ys[k*YPITCH + slot], slot = row-permuted
    float* Gs = (float*)(smem_buf + GS_OFF);   // Gs[k*HALF + tt]
    float* Cs = (float*)(smem_buf + CS_OFF);
    float* Co = (float*)smem_buf;              // Co[row*CPITCH + tt] (epilogue, aliases Ys/Gs)

    const int half  = blockIdx.x & 1;
    const int rb    = blockIdx.x >> 1;
    const int toff  = half * HALF;
    const int brow0 = rb * 128;

    // --- Stage G half-slice + C ---
    for (int i = threadIdx.x; i < P * (HALF / 4); i += TPB) {
        const int kk = i / (HALF / 4);
        const int j4 = i - kk * (HALF / 4);
        *(float4*)(Gs + kk * HALF + j4 * 4) =
            *(const float4*)(g_G + kk * FLEN + toff + j4 * 4);
    }
    if (threadIdx.x < HALF) Cs[threadIdx.x] = g_C[toff + threadIdx.x];

    // --- Stage Y tile transposed + ROW-PERMUTED: row r -> slot 4*(r&31) + (r>>5)
    // so each thread's LDS.128 a-frag yields rows {tr, tr+32, tr+64, tr+96}. ---
    for (int i = threadIdx.x; i < 128 * (P / 4); i += TPB) {
        const int r  = i / (P / 4);
        const int j4 = i - r * (P / 4);
        const int gr = brow0 + r;
        float4 v = (gr < B)
            ? *(const float4*)(enc_l + (size_t)gr * HIST + HOFF + j4 * 4)
            : make_float4(0.f, 0.f, 0.f, 0.f);
        const int p = 4 * (r & 31) + (r >> 5);
        Ys[(4 * j4 + 0) * YPITCH + p] = v.x;
        Ys[(4 * j4 + 1) * YPITCH + p] = v.y;
        Ys[(4 * j4 + 2) * YPITCH + p] = v.z;
        Ys[(4 * j4 + 3) * YPITCH + p] = v.w;
    }
    __syncthreads();

    const int tr = threadIdx.x & 31;     // lane: owns rows tr + 32*ri
    const int tc = threadIdx.x >> 5;     // warp id: t = tc*12 .. +11
    const int t0 = tc * 12;

    // acc[ri][j]: 4 rows x 6 packed t-pairs, init from C
    ull acc[4][6];
    {
        const ull* cp = (const ull*)(Cs + t0);
        ull c0 = cp[0], c1 = cp[1], c2 = cp[2], c3 = cp[3], c4 = cp[4], c5 = cp[5];
#pragma unroll
        for (int ri = 0; ri < 4; ri++) {
            acc[ri][0] = c0; acc[ri][1] = c1; acc[ri][2] = c2;
            acc[ri][3] = c3; acc[ri][4] = c4; acc[ri][5] = c5;
        }
    }

#pragma unroll 4
    for (int k = 0; k < P; ++k) {
        const float4 av = *(const float4*)(Ys + k * YPITCH + 4 * tr);   // rows tr+32*{0..3}
        const ull* gp = (const ull*)(Gs + k * HALF + t0);               // warp-broadcast
        const ull g0 = gp[0], g1 = gp[1], g2 = gp[2], g3 = gp[3], g4 = gp[4], g5 = gp[5];

        const ull y0 = pack2(av.x, av.x);
        const ull y1 = pack2(av.y, av.y);
        const ull y2 = pack2(av.z, av.z);
        const ull y3 = pack2(av.w, av.w);

        acc[0][0] = ffma2(g0, y0, acc[0][0]); acc[0][1] = ffma2(g1, y0, acc[0][1]);
        acc[0][2] = ffma2(g2, y0, acc[0][2]); acc[0][3] = ffma2(g3, y0, acc[0][3]);
        acc[0][4] = ffma2(g4, y0, acc[0][4]); acc[0][5] = ffma2(g5, y0, acc[0][5]);
        acc[1][0] = ffma2(g0, y1, acc[1][0]); acc[1][1] = ffma2(g1, y1, acc[1][1]);
        acc[1][2] = ffma2(g2, y1, acc[1][2]); acc[1][3] = ffma2(g3, y1, acc[1][3]);
        acc[1][4] = ffma2(g4, y1, acc[1][4]); acc[1][5] = ffma2(g5, y1, acc[1][5]);
        acc[2][0] = ffma2(g0, y2, acc[2][0]); acc[2][1] = ffma2(g1, y2, acc[2][1]);
        acc[2][2] = ffma2(g2, y2, acc[2][2]); acc[2][3] = ffma2(g3, y2, acc[2][3]);
        acc[2][4] = ffma2(g4, y2, acc[2][4]); acc[2][5] = ffma2(g5, y2, acc[2][5]);
        acc[3][0] = ffma2(g0, y3, acc[3][0]); acc[3][1] = ffma2(g1, y3, acc[3][1]);
        acc[3][2] = ffma2(g2, y3, acc[3][2]); acc[3][3] = ffma2(g3, y3, acc[3][3]);
        acc[3][4] = ffma2(g4, y3, acc[3][4]); acc[3][5] = ffma2(g5, y3, acc[3][5]);
    }

    // --- Epilogue 1: stage mu tile into smem (aliases Ys/Gs -> sync first) ---
    __syncthreads();
#pragma unroll
    for (int ri = 0; ri < 4; ri++) {
        const int rl = tr + 32 * ri;                 // local row
        ull* cw = (ull*)(Co + rl * CPITCH + t0);     // 8B-aligned
#pragma unroll
        for (int j = 0; j < 6; j++) cw[j] = acc[ri][j];
    }
    __syncthreads();

    // --- Epilogue 2: coalesced stores. Lanes cover consecutive float4 in a row. ---
    const float lv = g_lv;
    const float4 lv4 = make_float4(lv, lv, lv, lv);
    const size_t lvbase = (size_t)B * FLEN;
#pragma unroll 2
    for (int i = threadIdx.x; i < 128 * (HALF / 4); i += TPB) {
        const int r = i / (HALF / 4);
        const int c = i - r * (HALF / 4);
        const int gr = brow0 + r;
        if (gr < B) {
            const float4 v = *(const float4*)(Co + r * CPITCH + 4 * c);
            *(float4*)(out + (size_t)gr * FLEN + toff + 4 * c) = v;
            *(float4*)(out + lvbase + (size_t)gr * FLEN + toff + 4 * c) = lv4;
        }
    }
}

// ---------------------------------------------------------------------------
extern "C" void kernel_launch(void* const* d_in, const int* in_sizes, int n_in,
                              void* d_out, int out_size) {
    const float* enc_l      = (const float*)d_in[0];
    // d_in[1..3] = enc_t, enc_w, enc_s (unused by the reference)
    const float* phi        = (const float*)d_in[4];
    const float* bias       = (const float*)d_in[5];
    const float* log_sigma2 = (const float*)d_in[6];
    const float* mu         = (const float*)d_in[7];
    const float* sigma      = (const float*)d_in[8];

    const int B = in_sizes[0] / HIST;

    precompute_kernel<<<1, 64>>>(phi, bias, log_sigma2, mu, sigma);

    const int nblk = 2 * ((B + 127) / 128);   // x2: t-halves
    forecast_kernel<<<nblk, TPB>>>(enc_l, (float*)d_out, B);
}

// round 6
// speedup vs baseline: 1.4275x; 1.0385x over previous
#include <cuda_runtime.h>
#include <cstdint>
#include <math.h>

// Problem constants
#define P     48
#define FLEN  168
#define TCH   56     // t-chunk per CTA (3 chunks cover 168)
#define HIST  336
#define HOFF  288    // HIST - P

// Precomputed affine map: out[b,t] = g_C[t] + sum_k g_G[k*FLEN+t] * enc_l[b*HIST+HOFF+k]
__device__ float g_G[P * FLEN];
__device__ float g_C[FLEN];
__device__ float g_lv;

typedef unsigned long long ull;

__device__ __forceinline__ ull pack2(float a, float b) {
    ull r; asm("mov.b64 %0, {%1, %2};" : "=l"(r) : "f"(a), "f"(b)); return r;
}
// Packed fp32x2 FMA (Blackwell 2x fp32 path; only emitted from PTX fma.rn.f32x2)
__device__ __forceinline__ ull ffma2(ull a, ull b, ull c) {
    ull d; asm("fma.rn.f32x2 %0, %1, %2, %3;" : "=l"(d) : "l"(a), "l"(b), "l"(c)); return d;
}

// ---------------------------------------------------------------------------
// Kernel 1: tiny precompute of the affine map (G, C, logvar const).
// ---------------------------------------------------------------------------
__global__ void precompute_kernel(const float* __restrict__ phi,
                                  const float* __restrict__ bias,
                                  const float* __restrict__ log_sigma2,
                                  const float* __restrict__ mu_p,
                                  const float* __restrict__ sigma_p) {
    __shared__ float h[P + 1][221];   // 221 odd pitch -> conflict-free
    const int k = threadIdx.x;

    float ph[P];
#pragma unroll
    for (int j = 0; j < P; j++) ph[j] = phi[j];

    if (k <= P) {
#pragma unroll
        for (int i = 0; i < P; i++) h[k][i] = (k == i) ? 1.0f : 0.0f;  // k==P row: zeros
        const float b0 = (k == P) ? bias[0] : 0.0f;
        for (int t = 0; t < FLEN; t++) {
            float s0 = 0.f, s1 = 0.f, s2 = 0.f, s3 = 0.f;
#pragma unroll
            for (int j = 0; j < P; j += 4) {
                s0 += ph[j + 0] * h[k][t + j + 0];
                s1 += ph[j + 1] * h[k][t + j + 1];
                s2 += ph[j + 2] * h[k][t + j + 2];
                s3 += ph[j + 3] * h[k][t + j + 3];
            }
            h[k][P + t] = b0 + ((s0 + s1) + (s2 + s3));
        }
    }
    __syncthreads();

    const float mu = *mu_p;
    const float sg = *sigma_p;

    for (int t = threadIdx.x; t < FLEN; t += blockDim.x) {
        float sum = 0.0f;
        for (int kk = 0; kk < P; kk++) sum += h[kk][P + t];
        g_C[t] = mu + sg * h[P][P + t] - mu * sum;
    }
    for (int idx = threadIdx.x; idx < P * FLEN; idx += blockDim.x) {
        const int kk = idx / FLEN;
        const int t  = idx - kk * FLEN;
        g_G[idx] = h[kk][P + t];
    }
    if (threadIdx.x == 0) g_lv = log_sigma2[0] + 2.0f * logf(sg);
}

// ---------------------------------------------------------------------------
// Kernel 2: register-blocked GEMM, tuned for occupancy + FMA density.
// 4 rows x 8 t per thread (acc = 16 ull = 32 regs), 3 t-chunks of 56,
// 4 CTAs/SM (28 warps) to hide LDS latency; unroll-8 k loop folds LDS
// offsets into immediates. Coalesced epilogue via smem restage (2-way
// conflict STS, contiguous STG).
// ---------------------------------------------------------------------------
#define TPB    224    // 32 row-lanes x 7 t-warps
#define YPITCH 132
#define COP    29     // Co row pitch in ull (58 floats): 2-way STS conflict only

#define YS_OFF 0
#define GS_OFF (P * YPITCH * 4)                  // 25344
#define CS_OFF (GS_OFF + P * TCH * 4)            // 36096
#define ML_BYTES (CS_OFF + TCH * 4)              // 36320
#define CO_BYTES (128 * COP * 8)                 // 29696
#define SMEM_BYTES (ML_BYTES > CO_BYTES ? ML_BYTES : CO_BYTES)

__global__ void __launch_bounds__(TPB, 4)
forecast_kernel(const float* __restrict__ enc_l, float* __restrict__ out, int B) {
    __shared__ __align__(16) char smem_buf[SMEM_BYTES];
    float* Ys = (float*)(smem_buf + YS_OFF);   // Ys[k*YPITCH + slot], row-permuted
    float* Gs = (float*)(smem_buf + GS_OFF);   // Gs[k*TCH + tt]
    float* Cs = (float*)(smem_buf + CS_OFF);
    ull*   Co = (ull*)smem_buf;                // epilogue restage (aliases Ys/Gs)

    const int chunk = blockIdx.x % 3;
    const int rb    = blockIdx.x / 3;
    const int toff  = chunk * TCH;
    const int brow0 = rb * 128;

    // --- Stage G chunk + C chunk ---
    for (int i = threadIdx.x; i < P * (TCH / 4); i += TPB) {
        const int kk = i / (TCH / 4);
        const int j4 = i - kk * (TCH / 4);
        *(float4*)(Gs + kk * TCH + j4 * 4) =
            *(const float4*)(g_G + kk * FLEN + toff + j4 * 4);
    }
    if (threadIdx.x < TCH) Cs[threadIdx.x] = g_C[toff + threadIdx.x];

    // --- Stage Y tile transposed + row-permuted: row r -> slot 4*(r&31)+(r>>5)
    // so each lane's LDS.128 a-frag yields rows {tr, tr+32, tr+64, tr+96}. ---
    for (int i = threadIdx.x; i < 128 * (P / 4); i += TPB) {
        const int r  = i / (P / 4);
        const int j4 = i - r * (P / 4);
        const int gr = brow0 + r;
        float4 v = (gr < B)
            ? *(const float4*)(enc_l + (size_t)gr * HIST + HOFF + j4 * 4)
            : make_float4(0.f, 0.f, 0.f, 0.f);
        const int p = 4 * (r & 31) + (r >> 5);
        Ys[(4 * j4 + 0) * YPITCH + p] = v.x;
        Ys[(4 * j4 + 1) * YPITCH + p] = v.y;
        Ys[(4 * j4 + 2) * YPITCH + p] = v.z;
        Ys[(4 * j4 + 3) * YPITCH + p] = v.w;
    }
    __syncthreads();

    const int tr = threadIdx.x & 31;    // lane: rows tr + 32*ri
    const int tc = threadIdx.x >> 5;    // warp: t = tc*8 .. +7
    const int t0 = tc * 8;

    // acc[ri][j]: 4 rows x 4 packed t-pairs
    ull acc[4][4];
    {
        const ull* cp = (const ull*)(Cs + t0);
        const ull c0 = cp[0], c1 = cp[1], c2 = cp[2], c3 = cp[3];
#pragma unroll
        for (int ri = 0; ri < 4; ri++) {
            acc[ri][0] = c0; acc[ri][1] = c1; acc[ri][2] = c2; acc[ri][3] = c3;
        }
    }

    const float* ya = Ys + 4 * tr;
    const ull*   ga = (const ull*)(Gs + t0);

#pragma unroll 8
    for (int k = 0; k < P; ++k) {
        const float4 av = *(const float4*)(ya + k * YPITCH);       // 4 rows' y[k]
        const ull* gp = ga + k * (TCH / 2);                        // warp-broadcast
        const ull g0 = gp[0], g1 = gp[1], g2 = gp[2], g3 = gp[3];

        const ull y0 = pack2(av.x, av.x);
        const ull y1 = pack2(av.y, av.y);
        const ull y2 = pack2(av.z, av.z);
        const ull y3 = pack2(av.w, av.w);

        acc[0][0] = ffma2(g0, y0, acc[0][0]); acc[0][1] = ffma2(g1, y0, acc[0][1]);
        acc[0][2] = ffma2(g2, y0, acc[0][2]); acc[0][3] = ffma2(g3, y0, acc[0][3]);
        acc[1][0] = ffma2(g0, y1, acc[1][0]); acc[1][1] = ffma2(g1, y1, acc[1][1]);
        acc[1][2] = ffma2(g2, y1, acc[1][2]); acc[1][3] = ffma2(g3, y1, acc[1][3]);
        acc[2][0] = ffma2(g0, y2, acc[2][0]); acc[2][1] = ffma2(g1, y2, acc[2][1]);
        acc[2][2] = ffma2(g2, y2, acc[2][2]); acc[2][3] = ffma2(g3, y2, acc[2][3]);
        acc[3][0] = ffma2(g0, y3, acc[3][0]); acc[3][1] = ffma2(g1, y3, acc[3][1]);
        acc[3][2] = ffma2(g2, y3, acc[3][2]); acc[3][3] = ffma2(g3, y3, acc[3][3]);
    }

    // --- Epilogue 1: restage mu tile in smem (2-way-conflict STS.64) ---
    __syncthreads();
#pragma unroll
    for (int ri = 0; ri < 4; ri++) {
        const int rl = tr + 32 * ri;                 // local row (permuted ownership)
        ull* cw = Co + rl * COP + tc * 4;
        cw[0] = acc[ri][0]; cw[1] = acc[ri][1];
        cw[2] = acc[ri][2]; cw[3] = acc[ri][3];
    }
    __syncthreads();

    // --- Epilogue 2: coalesced stores ---
    const size_t lvbase = (size_t)B * FLEN;
#pragma unroll 2
    for (int i = threadIdx.x; i < 128 * (TCH / 2); i += TPB) {
        const int r = i / (TCH / 2);
        const int c = i - r * (TCH / 2);
        const int gr = brow0 + r;
        if (gr < B)
            *(ull*)(out + (size_t)gr * FLEN + toff + 2 * c) = Co[r * COP + c];
    }
    const float lv = g_lv;
    const float4 lv4 = make_float4(lv, lv, lv, lv);
#pragma unroll 2
    for (int i = threadIdx.x; i < 128 * (TCH / 4); i += TPB) {
        const int r = i / (TCH / 4);
        const int c = i - r * (TCH / 4);
        const int gr = brow0 + r;
        if (gr < B)
            *(float4*)(out + lvbase + (size_t)gr * FLEN + toff + 4 * c) = lv4;
    }
}

// ---------------------------------------------------------------------------
extern "C" void kernel_launch(void* const* d_in, const int* in_sizes, int n_in,
                              void* d_out, int out_size) {
    const float* enc_l      = (const float*)d_in[0];
    // d_in[1..3] = enc_t, enc_w, enc_s (unused by the reference)
    const float* phi        = (const float*)d_in[4];
    const float* bias       = (const float*)d_in[5];
    const float* log_sigma2 = (const float*)d_in[6];
    const float* mu         = (const float*)d_in[7];
    const float* sigma      = (const float*)d_in[8];

    const int B = in_sizes[0] / HIST;

    precompute_kernel<<<1, 64>>>(phi, bias, log_sigma2, mu, sigma);

    const int nblk = 3 * ((B + 127) / 128);   // x3: t-chunks of 56
    forecast_kernel<<<nblk, TPB>>>(enc_l, (float*)d_out, B);
}